// round 5
// baseline (speedup 1.0000x reference)
#include <cuda_runtime.h>
#include <cuda_bf16.h>
#include <stdint.h>

#define WS 7
#define DROP_PROB 0.1f
#define H 256
#define W 256
#define HC (H - WS + 1)   // 250
#define WC (W - WS + 1)   // 250
#define BC (16 * 64)      // batch * channels = 1024
#define N4 (BC * H * W / 4)          // 16,777,216 float4 total
#define WORDS_PER_ROW 8              // 256 cols / 32 bits
#define NBITS_WORDS (H * WORDS_PER_ROW)  // 2048 u32 = 8 KB

// The [H, W] "dropped" mask as a bitmask: bit (col&31) of word [row*8 + col/32].
__device__ uint32_t g_bits[NBITS_WORDS];

// ---------------------------------------------------------------------------
// Kernel 1: build the dropped-pixel bitmask. ONE block, 256 threads (8 warps).
//   Phase A: decision bits dec[r] (anchor r, 250 cols) via warp ballots.
//   Phase B: horizontal dilation by WS (anchor aw covers pixels [aw, aw+6])
//            = left-smear of bits by 6, with cross-word carry via 64-bit.
//   Phase C: vertical dilation: pixel row h ORs anchor rows [h-6, h] clamped.
// ---------------------------------------------------------------------------
__global__ void build_bits_kernel(const float* __restrict__ u) {
    __shared__ uint32_t dec_s[HC * WORDS_PER_ROW];   // 250*8 words
    __shared__ uint32_t hdil_s[HC * WORDS_PER_ROW];  // 250*8 words

    int tid  = threadIdx.x;
    int lane = tid & 31;
    int warp = tid >> 5;

    // Phase A: one warp per anchor row (strided), 8 ballots per row.
    for (int r = warp; r < HC; r += 8) {
        const float* __restrict__ urow = u + r * WC;
        #pragma unroll
        for (int w = 0; w < WORDS_PER_ROW; ++w) {
            int col = (w << 5) + lane;
            bool pred = (col < WC) && (urow[col] < DROP_PROB);
            uint32_t bits = __ballot_sync(0xFFFFFFFFu, pred);
            if (lane == 0) dec_s[r * WORDS_PER_ROW + w] = bits;
        }
    }
    __syncthreads();

    // Phase B: horizontal left-smear by 6 with carry-in from the lower word.
    for (int idx = tid; idx < HC * WORDS_PER_ROW; idx += 256) {
        int i = idx & (WORDS_PER_ROW - 1);
        uint32_t hi = dec_s[idx];
        uint32_t lo = (i == 0) ? 0u : dec_s[idx - 1];
        uint64_t v = ((uint64_t)hi << 32) | (uint64_t)lo;
        // smear left by 6: shifts {0..6}
        v |= v << 1;   // covers 0-1
        v |= v << 2;   // covers 0-3
        v |= v << 3;   // covers 0-6
        hdil_s[idx] = (uint32_t)(v >> 32);
    }
    __syncthreads();

    // Phase C: vertical OR over up to 7 anchor rows, write global bitmask.
    for (int idx = tid; idx < NBITS_WORDS; idx += 256) {
        int h = idx >> 3;                 // pixel row 0..255
        int i = idx & (WORDS_PER_ROW - 1);
        int a0 = h - (WS - 1); if (a0 < 0) a0 = 0;
        int a1 = h;            if (a1 > HC - 1) a1 = HC - 1;
        uint32_t acc = 0;
        for (int ah = a0; ah <= a1; ++ah)
            acc |= hdil_s[ah * WORDS_PER_ROW + i];
        g_bits[idx] = acc;
    }
}

// ---------------------------------------------------------------------------
// Kernel 2: out = dropped ? 0 : x, streamed as float4 with streaming cache
// hints. Each block stages the full 8 KB bitmask in smem, then processes a
// contiguous chunk of CHUNK float4.
// CHUNK (4096) divides the per-image float4 count (16384) and blocks are
// aligned to CHUNK, so a block never crosses an image boundary: the local
// mask index is (base & 16383) + k*256, no per-iteration wrap possible.
// ---------------------------------------------------------------------------
#define APPLY_BLOCKS 4096
#define CHUNK (N4 / APPLY_BLOCKS)    // 4096 float4 per block
#define ITERS (CHUNK / 256)          // 16 per thread

__global__ void __launch_bounds__(256) apply_mask_kernel(
        const float4* __restrict__ x, float4* __restrict__ out) {
    __shared__ uint32_t bits[NBITS_WORDS];
    for (int k = threadIdx.x; k < NBITS_WORDS; k += 256)
        bits[k] = g_bits[k];
    __syncthreads();

    int base  = blockIdx.x * CHUNK + threadIdx.x;
    int local = base & (H * W / 4 - 1);           // float4 index within image
    #pragma unroll
    for (int k = 0; k < ITERS; ++k) {
        int i  = base + (k << 8);
        int li = local + (k << 8);                // stays < 16384 (see above)
        int row  = li >> 6;                       // / 64 float4 per row
        int colw = li & 63;                       // float4 col
        uint32_t word = bits[(row << 3) + (colw >> 3)];
        uint32_t nib  = (word >> ((colw & 7) << 2)) & 0xFu;

        float4 xv = __ldcs(&x[i]);
        float4 ov;
        ov.x = (nib & 1u) ? 0.0f : xv.x;
        ov.y = (nib & 2u) ? 0.0f : xv.y;
        ov.z = (nib & 4u) ? 0.0f : xv.z;
        ov.w = (nib & 8u) ? 0.0f : xv.w;
        __stcs(&out[i], ov);
    }
}

extern "C" void kernel_launch(void* const* d_in, const int* in_sizes, int n_in,
                              void* d_out, int out_size) {
    const float* x = (const float*)d_in[0];   // [16, 64, 256, 256] fp32
    const float* u = (const float*)d_in[1];   // [250, 250] fp32
    float* out = (float*)d_out;

    build_bits_kernel<<<1, 256>>>(u);
    apply_mask_kernel<<<APPLY_BLOCKS, 256>>>(
        reinterpret_cast<const float4*>(x),
        reinterpret_cast<float4*>(out));
}

// round 6
// speedup vs baseline: 1.2366x; 1.2366x over previous
#include <cuda_runtime.h>
#include <cuda_bf16.h>
#include <stdint.h>

#define WS 7
#define DROP_PROB 0.1f
#define H 256
#define W 256
#define HC (H - WS + 1)   // 250
#define WC (W - WS + 1)   // 250
#define BC (16 * 64)      // batch * channels = 1024
#define N4 (BC * H * W / 4)          // 16,777,216 float4 total
#define WORDS_PER_ROW 8              // 256 cols / 32 bits

// The [H, W] keep-mask as floats (1.0 keep / 0.0 drop). 256 KB, L2-resident.
__device__ float g_mask[H * W];

// ---------------------------------------------------------------------------
// Kernel 1: build the float keep-mask. 256 blocks (one per pixel row h),
// 256 threads (8 warps). Warp r (r < na) ballots anchor row a0+r of u,
// horizontally dilates its 250 decision bits by WS-1=6 (left-smear with
// cross-word carry via 64-bit), stores 8 words to smem. Then the rows are
// OR-ed vertically and expanded to 256 floats for row h.
//
// Coverage note: anchor col aw covers pixel cols [aw, aw+6]; max aw=249
// covers up to col 255, which the smear handles inside word 7. Pixel rows
// >= 250 are covered by clamping the anchor-row range to [h-6, 249].
// ---------------------------------------------------------------------------
__global__ void __launch_bounds__(256) build_mask_kernel(const float* __restrict__ u) {
    __shared__ uint32_t hd[WS][WORDS_PER_ROW];   // horizontally-dilated rows
    __shared__ uint32_t orw[WORDS_PER_ROW];      // final OR per word

    int h    = blockIdx.x;
    int tid  = threadIdx.x;
    int lane = tid & 31;
    int warp = tid >> 5;

    int a0 = h - (WS - 1); if (a0 < 0) a0 = 0;
    int a1 = h;            if (a1 > HC - 1) a1 = HC - 1;
    int na = a1 - a0 + 1;                        // 1..7 anchor rows needed

    if (warp < na) {
        const float* __restrict__ urow = u + (a0 + warp) * WC;
        uint32_t dec[WORDS_PER_ROW];
        #pragma unroll
        for (int w = 0; w < WORDS_PER_ROW; ++w) {
            int col = (w << 5) + lane;
            bool pred = (col < WC) && (urow[col] < DROP_PROB);
            dec[w] = __ballot_sync(0xFFFFFFFFu, pred);   // same in all lanes
        }
        // lanes 0..7: lane i smears word i (carry-in from word i-1)
        if (lane < WORDS_PER_ROW) {
            uint32_t hi = dec[0], lo = 0;
            #pragma unroll
            for (int w = 0; w < WORDS_PER_ROW; ++w) {
                if (lane == w) { hi = dec[w]; lo = (w == 0) ? 0u : dec[w - 1]; }
            }
            uint64_t v = ((uint64_t)hi << 32) | (uint64_t)lo;
            v |= v << 1;   // smear left by 1   (covers shifts 0-1)
            v |= v << 2;   //                + 2 (covers 0-3)
            v |= v << 3;   //                + 3 (covers 0-6)
            hd[warp][lane] = (uint32_t)(v >> 32);
        }
    }
    __syncthreads();

    if (tid < WORDS_PER_ROW) {
        uint32_t acc = 0;
        for (int r = 0; r < na; ++r) acc |= hd[r][tid];
        orw[tid] = acc;
    }
    __syncthreads();

    // Expand: thread t -> pixel col t of row h.
    uint32_t word = orw[tid >> 5];
    g_mask[(h << 8) + tid] = ((word >> (tid & 31)) & 1u) ? 0.0f : 1.0f;
}

// ---------------------------------------------------------------------------
// Kernel 2 (EXACT R2 version — measured 77.8us @ 76.8% DRAM): out = x * mask,
// grid-stride float4. Mask float4 index = i & 16383 (one AND, no div/mod).
// ---------------------------------------------------------------------------
__global__ void apply_mask_kernel(const float4* __restrict__ x,
                                  float4* __restrict__ out,
                                  int n4) {
    const float4* __restrict__ mask4 = reinterpret_cast<const float4*>(g_mask);
    int stride = gridDim.x * blockDim.x;
    for (int i = blockIdx.x * blockDim.x + threadIdx.x; i < n4; i += stride) {
        float4 xv = x[i];
        float4 mv = mask4[i & (H * W / 4 - 1)];
        float4 ov;
        ov.x = xv.x * mv.x;
        ov.y = xv.y * mv.y;
        ov.z = xv.z * mv.z;
        ov.w = xv.w * mv.w;
        out[i] = ov;
    }
}

extern "C" void kernel_launch(void* const* d_in, const int* in_sizes, int n_in,
                              void* d_out, int out_size) {
    const float* x = (const float*)d_in[0];   // [16, 64, 256, 256] fp32
    const float* u = (const float*)d_in[1];   // [250, 250] fp32
    float* out = (float*)d_out;

    build_mask_kernel<<<H, 256>>>(u);         // 256 blocks, one per pixel row

    int n4 = BC * H * W / 4;                  // 16,777,216 float4
    apply_mask_kernel<<<16384, 256>>>(
        reinterpret_cast<const float4*>(x),
        reinterpret_cast<float4*>(out), n4);
}

// round 9
// speedup vs baseline: 1.2380x; 1.0011x over previous
#include <cuda_runtime.h>
#include <cuda_bf16.h>
#include <stdint.h>

#define WS 7
#define DROP_PROB 0.1f
#define H 256
#define W 256
#define HC (H - WS + 1)   // 250
#define WC (W - WS + 1)   // 250
#define BC (16 * 64)      // batch * channels = 1024
#define N4 (BC * H * W / 4)          // 16,777,216 float4 total
#define WORDS_PER_ROW 8              // 256 cols / 32 bits

#define BLOCKS 16384
#define THREADS 256
#define STRIDE (BLOCKS * THREADS)    // 4,194,304 — multiple of 16384!
#define KITERS (N4 / STRIDE)         // 4

// ---------------------------------------------------------------------------
// Fused kernel. Grid-stride with stride a multiple of the per-image float4
// count (16384), so each block touches exactly ONE 256-float4 local window
// = 4 consecutive image rows, identical across all KITERS iterations.
//
// Phase 1 (per block): build the dilated drop bits for those 4 rows.
//   - anchor rows needed: [r0-6, r0+3] clamped to [0, 249]  (<= 10 rows)
//   - warp w ballots anchor rows a_start+w and a_start+w+8 (8 ballots each,
//     one per 32-col word; cols >= 250 padded 0)
//   - horizontal dilation by 6: 64-bit left-smear with cross-word carry,
//     done by lanes 0..7 of the owning warp -> hd[row][8] in smem
// Phase 2 (per thread): OR hd over its pixel row's anchor range at its word,
//   extract the 4-bit nibble for its float4 column — computed ONCE.
// Phase 3: 4x { load float4, zero lanes per nibble, store }.
// ---------------------------------------------------------------------------
__global__ void __launch_bounds__(THREADS) fused_dropout_kernel(
        const float4* __restrict__ x, float4* __restrict__ out,
        const float* __restrict__ u) {
    __shared__ uint32_t hd[10][WORDS_PER_ROW];   // dilated anchor rows

    int tid  = threadIdx.x;
    int lane = tid & 31;
    int warp = tid >> 5;

    int base = blockIdx.x * THREADS;             // 256-aligned
    int L    = base & (H * W / 4 - 1);           // local float4 window start
    int r0   = L >> 6;                           // first of 4 pixel rows

    int a_start = r0 - (WS - 1); if (a_start < 0) a_start = 0;
    int a_end   = r0 + 3;        if (a_end > HC - 1) a_end = HC - 1;
    int nrows   = a_end - a_start + 1;           // <= 10

    // Phase 1: ballots + horizontal smear. Warp w covers relative rows w, w+8.
    #pragma unroll
    for (int pass = 0; pass < 2; ++pass) {
        int rr = warp + (pass << 3);             // 0..7, 8..15
        if (rr < nrows) {
            const float* __restrict__ urow = u + (a_start + rr) * WC;
            uint32_t dec[WORDS_PER_ROW];
            #pragma unroll
            for (int w = 0; w < WORDS_PER_ROW; ++w) {
                int col = (w << 5) + lane;
                bool pred = (col < WC) && (urow[col] < DROP_PROB);
                dec[w] = __ballot_sync(0xFFFFFFFFu, pred);  // uniform in warp
            }
            if (lane < WORDS_PER_ROW) {
                uint32_t hi = dec[0], lo = 0u;
                #pragma unroll
                for (int w = 0; w < WORDS_PER_ROW; ++w)
                    if (lane == w) { hi = dec[w]; lo = (w == 0) ? 0u : dec[w - 1]; }
                uint64_t v = ((uint64_t)hi << 32) | (uint64_t)lo;
                v |= v << 1;   // smear left by 6 total:
                v |= v << 2;   //   1+2+3 covers shifts 0..6
                v |= v << 3;
                hd[rr][lane] = (uint32_t)(v >> 32);
            }
        }
    }
    __syncthreads();

    // Phase 2: per-thread nibble (same for every k iteration).
    int row  = r0 + (tid >> 6);                  // this thread's pixel row
    int colw = tid & 63;                         // float4 column 0..63
    int wa0  = row - (WS - 1); if (wa0 < a_start) wa0 = a_start;
    int wa1  = row;            if (wa1 > a_end)   wa1 = a_end;
    uint32_t word = 0;
    for (int a = wa0; a <= wa1; ++a)
        word |= hd[a - a_start][colw >> 3];
    uint32_t nib = (word >> ((colw & 7) << 2)) & 0xFu;

    // Phase 3: stream 4 float4.
    int i = base + tid;
    #pragma unroll
    for (int k = 0; k < KITERS; ++k) {
        float4 xv = x[i];
        float4 ov;
        ov.x = (nib & 1u) ? 0.0f : xv.x;
        ov.y = (nib & 2u) ? 0.0f : xv.y;
        ov.z = (nib & 4u) ? 0.0f : xv.z;
        ov.w = (nib & 8u) ? 0.0f : xv.w;
        out[i] = ov;
        i += STRIDE;
    }
}

extern "C" void kernel_launch(void* const* d_in, const int* in_sizes, int n_in,
                              void* d_out, int out_size) {
    const float* x = (const float*)d_in[0];   // [16, 64, 256, 256] fp32
    const float* u = (const float*)d_in[1];   // [250, 250] fp32
    float* out = (float*)d_out;

    fused_dropout_kernel<<<BLOCKS, THREADS>>>(
        reinterpret_cast<const float4*>(x),
        reinterpret_cast<float4*>(out), u);
}